// round 1
// baseline (speedup 1.0000x reference)
#include <cuda_runtime.h>
#include <cstdint>

// nu_grid_sampler_simple: out[b,c,n] = x[b,c,px,py]
//   px = int(clip(coords[b,n,1]*(NX-1), 0, NX))
//   py = int(clip(coords[b,n,0]*(NY-1), 0, NY))
// x: (B=8, C=128, NX=256, NY=256) f32, coords: (B, N=32768, 2) f32
// out: (B, C, N) f32
//
// Strategy: one thread per (b, n). Compute the flat pixel index once from a
// coalesced float2 coords load, then loop all C=128 channels. Reads are
// inherently scattered (stride 256KB across channels), but the same index is
// reused 128x (no redundant index math / coords traffic), writes are fully
// coalesced (contiguous in n), and concurrent blocks walk channels in the
// same order so the instantaneous L2 working set is ~2MB -> exploit the ~4x
// average sector reuse (32768 points over 8192 32B-sectors per plane).

#ifndef GS_B
#define GS_B 8
#define GS_C 128
#define GS_NX 256
#define GS_NY 256
#define GS_N 32768
#endif

__global__ __launch_bounds__(256, 8)
void nu_grid_sampler_kernel(const float* __restrict__ x,
                            const float* __restrict__ coords,
                            float* __restrict__ out) {
    const int n = blockIdx.x * blockDim.x + threadIdx.x;   // point index
    const int b = blockIdx.y;                               // batch

    // coalesced 8B load of (coord_y, coord_x) pair
    const float2 co = reinterpret_cast<const float2*>(coords)[(size_t)b * GS_N + n];

    // replicate reference math exactly: scale by (dim-1), clamp to [0, dim], trunc
    float pxf = fminf(fmaxf(co.y * (float)(GS_NX - 1), 0.0f), (float)GS_NX);
    float pyf = fminf(fmaxf(co.x * (float)(GS_NY - 1), 0.0f), (float)GS_NY);
    int px = (int)pxf;
    int py = (int)pyf;
    int idx = px * GS_NY + py;
    // JAX take_along_axis clamps OOB; only reachable if coord >= 1.0 exactly
    idx = min(idx, GS_NX * GS_NY - 1);

    const float* __restrict__ xb = x + (size_t)b * GS_C * (GS_NX * GS_NY) + idx;
    float* __restrict__ ob       = out + (size_t)b * GS_C * GS_N + n;

    // 128 independent scattered loads (MLP ~16 via unroll), coalesced stores.
    #pragma unroll 16
    for (int c = 0; c < GS_C; ++c) {
        ob[(size_t)c * GS_N] = __ldg(xb + (size_t)c * (GS_NX * GS_NY));
    }
}

extern "C" void kernel_launch(void* const* d_in, const int* in_sizes, int n_in,
                              void* d_out, int out_size) {
    const float* x      = (const float*)d_in[0];   // (8,128,256,256) f32
    const float* coords = (const float*)d_in[1];   // (8,32768,2) f32
    float* out          = (float*)d_out;           // (8,128,32768) f32

    dim3 block(256);
    dim3 grid(GS_N / 256, GS_B);   // 128 x 8 = 1024 blocks
    nu_grid_sampler_kernel<<<grid, block>>>(x, coords, out);
}